// round 6
// baseline (speedup 1.0000x reference)
#include <cuda_runtime.h>
#include <cuda_fp16.h>
#include <math.h>
#include <stdint.h>

// Problem shapes (fixed by the dataset)
#define T_MAX 262144
#define B_MAX 4096
#define F_DIM 128
#define H_DIM 256
#define C_DIM 512
#define KV_DIM 512

// ---------------------------------------------------------------------------
// Scratch (allocation-free rule: __device__ globals)
// ---------------------------------------------------------------------------
__device__ __half g_ctxh[(size_t)B_MAX * C_DIM];      // 4 MB
__device__ float  g_v  [(size_t)T_MAX * H_DIM];       // 256 MB (v half of kv)
__device__ float  g_q  [(size_t)B_MAX * H_DIM];       // 4 MB
__device__ __half g_Wt1[H_DIM * F_DIM];               // W1^T [N][K] fp16
__device__ __half g_Wt2[H_DIM * H_DIM];
__device__ __half g_Wt3[KV_DIM * H_DIM];
__device__ __half g_Wtq[H_DIM * C_DIM];
__device__ float  g_logits[T_MAX];
__device__ int    g_segstart[B_MAX + 1];

// ---------------------------------------------------------------------------
// Helpers
// ---------------------------------------------------------------------------
__device__ __forceinline__ uint32_t smem_u32(const void* p) {
    uint32_t a;
    asm("{ .reg .u64 t; cvta.to.shared.u64 t, %1; cvt.u32.u64 %0, t; }" : "=r"(a) : "l"(p));
    return a;
}
__device__ __forceinline__ uint32_t u32_of_h2(__half2 h) {
    union { __half2 h2; uint32_t u; } c;
    c.h2 = h;
    return c.u;
}

#define CP_ASYNC16(dst, src) \
    asm volatile("cp.async.cg.shared.global [%0], [%1], 16;" :: "r"(dst), "l"(src) : "memory")
#define CP_COMMIT() asm volatile("cp.async.commit_group;" ::: "memory")
#define CP_WAIT0()  asm volatile("cp.async.wait_group 0;" ::: "memory")
#define CP_WAIT1()  asm volatile("cp.async.wait_group 1;" ::: "memory")

// mma.sync m16n8k16 fp16 -> fp32 accumulate
__device__ __forceinline__ void mma_fp16(float* c, const uint32_t* a, const uint32_t* b) {
    asm volatile(
        "mma.sync.aligned.m16n8k16.row.col.f32.f16.f16.f32 "
        "{%0,%1,%2,%3}, {%4,%5,%6,%7}, {%8,%9}, {%0,%1,%2,%3};"
        : "+f"(c[0]), "+f"(c[1]), "+f"(c[2]), "+f"(c[3])
        : "r"(a[0]), "r"(a[1]), "r"(a[2]), "r"(a[3]), "r"(b[0]), "r"(b[1]));
}

// ---------------------------------------------------------------------------
// Fused MLP kernel constants
// Activation buffers: [128 rows][132 u32] (264 halves; K data in first K/2 u32)
// 132 mod 32 == 4 -> fragment loads (addr = r*132 + tg [+4]) are conflict-free.
// Weight chunk buffers: [128 n][20 u32] as in round-4 GEMM.
// ---------------------------------------------------------------------------
#define AB_STRIDE 132
#define AB_U32    (128 * AB_STRIDE)          // 16896 u32 = 67584 B per buffer
#define WCHUNK_U32 (128 * 20)                // 2560 u32 = 10240 B per stage
#define SMEM_FUSED_BYTES ((2 * AB_U32 + 2 * WCHUNK_U32 + 128 + 128) * 4)

// Per-N-half GEMM: acc += Abuf[128 x K] @ W[128 x K]^T, weights streamed via cp.async.
__device__ __forceinline__ void run_half(
    const uint32_t* __restrict__ Abuf,   // stationary activations, stride AB_STRIDE
    uint32_t* __restrict__ wbuf,         // 2 * WCHUNK_U32
    uint32_t wbuf_addr,                  // smem byte address of wbuf
    const __half* __restrict__ W,        // global [128][K] (this half's rows)
    int K, int tid, float acc[2][8][4])
{
    const int wid = tid >> 5, lane = tid & 31;
    const int g = lane >> 2, tg = lane & 3;
    const int wm = wid >> 1, wn = wid & 1;
    const int nk = K >> 5;

    auto load_chunk = [&](int s, int c) {
        const __half* src = W + c * 32;
        uint32_t base = wbuf_addr + (uint32_t)s * (WCHUNK_U32 * 4);
#pragma unroll
        for (int i = 0; i < 2; i++) {
            int idx = tid + i * 256;
            int row = idx >> 2, k8 = idx & 3;
            CP_ASYNC16(base + (uint32_t)(row * 80 + k8 * 16),
                       src + (size_t)row * K + k8 * 8);
        }
        CP_COMMIT();
    };

    load_chunk(0, 0);
    for (int c = 0; c < nk; c++) {
        if (c + 1 < nk) { load_chunk((c + 1) & 1, c + 1); CP_WAIT1(); }
        else            { CP_WAIT0(); }
        __syncthreads();
        const uint32_t* Ws = wbuf + (c & 1) * WCHUNK_U32;
#pragma unroll
        for (int ks = 0; ks < 2; ks++) {
            uint32_t a[2][4], b[8][2];
            const int kbA = c * 16 + ks * 8 + tg;
#pragma unroll
            for (int mf = 0; mf < 2; mf++) {
                int r = wm * 32 + mf * 16 + g;
                a[mf][0] = Abuf[r * AB_STRIDE + kbA];
                a[mf][1] = Abuf[(r + 8) * AB_STRIDE + kbA];
                a[mf][2] = Abuf[r * AB_STRIDE + kbA + 4];
                a[mf][3] = Abuf[(r + 8) * AB_STRIDE + kbA + 4];
            }
            const int kbW = ks * 8 + tg;
#pragma unroll
            for (int nf = 0; nf < 8; nf++) {
                int n = wn * 64 + nf * 8 + g;
                b[nf][0] = Ws[n * 20 + kbW];
                b[nf][1] = Ws[n * 20 + kbW + 4];
            }
#pragma unroll
            for (int mf = 0; mf < 2; mf++)
#pragma unroll
                for (int nf = 0; nf < 8; nf++)
                    mma_fp16(acc[mf][nf], a[mf], b[nf]);
        }
        __syncthreads();
    }
}

// ---------------------------------------------------------------------------
// Fused: objects -> h1 -> h2 -> {k-dot->logits, v->gmem}   (one 128-row tile/CTA)
// ---------------------------------------------------------------------------
__global__ __launch_bounds__(256, 1) void fused_mlp(
    const float* __restrict__ objects,
    const __half* __restrict__ W1t, const float* __restrict__ b1,
    const __half* __restrict__ W2t, const float* __restrict__ b2,
    const __half* __restrict__ W3t, const float* __restrict__ b3,
    const float* __restrict__ q, const int* __restrict__ seg,
    float* __restrict__ v_out, float* __restrict__ logits)
{
    extern __shared__ uint32_t smu[];
    uint32_t* bufA = smu;
    uint32_t* bufB = smu + AB_U32;
    uint32_t* wbuf = smu + 2 * AB_U32;
    int*   s_seg   = (int*)(smu + 2 * AB_U32 + 2 * WCHUNK_U32);
    float* s_logit = (float*)(s_seg + 128);

    const uint32_t wbuf_addr = smem_u32(wbuf);
    const int tid = threadIdx.x;
    const int wid = tid >> 5, lane = tid & 31;
    const int g = lane >> 2, tg = lane & 3;
    const int wm = wid >> 1, wn = wid & 1;
    const size_t t0 = (size_t)blockIdx.x * 128;

    if (tid < 128) { s_seg[tid] = seg[t0 + tid]; s_logit[tid] = 0.f; }

    // Stage 0: load objects tile [128 x 128] fp32 -> fp16 into bufA
    {
        const float* src = objects + t0 * F_DIM;
#pragma unroll
        for (int i = 0; i < 16; i++) {
            int idx = tid + i * 256;               // 4096 float4s
            int row = idx >> 5, c16 = idx & 31;    // 32 float4 per row
            float4 v = *reinterpret_cast<const float4*>(src + (size_t)row * F_DIM + c16 * 4);
            uint2 h;
            h.x = u32_of_h2(__floats2half2_rn(v.x, v.y));
            h.y = u32_of_h2(__floats2half2_rn(v.z, v.w));
            *reinterpret_cast<uint2*>(bufA + row * AB_STRIDE + c16 * 2) = h;
        }
    }
    __syncthreads();

    float acc[2][8][4];

    // Stage 1: h1 = relu(A0 @ W1 + b1) -> bufB (fp16)
#pragma unroll
    for (int nh = 0; nh < 2; nh++) {
#pragma unroll
        for (int mf = 0; mf < 2; mf++)
#pragma unroll
            for (int nf = 0; nf < 8; nf++)
#pragma unroll
                for (int j = 0; j < 4; j++) acc[mf][nf][j] = 0.f;
        run_half(bufA, wbuf, wbuf_addr, W1t + (size_t)nh * 128 * F_DIM, F_DIM, tid, acc);
#pragma unroll
        for (int mf = 0; mf < 2; mf++) {
            int r0 = wm * 32 + mf * 16 + g;
#pragma unroll
            for (int nf = 0; nf < 8; nf++) {
                int col = nh * 128 + wn * 64 + nf * 8 + tg * 2;
                float bb0 = __ldg(b1 + col), bb1 = __ldg(b1 + col + 1);
                float v0 = fmaxf(acc[mf][nf][0] + bb0, 0.f);
                float v1 = fmaxf(acc[mf][nf][1] + bb1, 0.f);
                float v2 = fmaxf(acc[mf][nf][2] + bb0, 0.f);
                float v3 = fmaxf(acc[mf][nf][3] + bb1, 0.f);
                int cu = col >> 1;
                bufB[r0 * AB_STRIDE + cu]       = u32_of_h2(__floats2half2_rn(v0, v1));
                bufB[(r0 + 8) * AB_STRIDE + cu] = u32_of_h2(__floats2half2_rn(v2, v3));
            }
        }
    }
    __syncthreads();

    // Stage 2: h2 = relu(h1 @ W2 + b2) -> bufA (fp16, overwrites objects)
#pragma unroll
    for (int nh = 0; nh < 2; nh++) {
#pragma unroll
        for (int mf = 0; mf < 2; mf++)
#pragma unroll
            for (int nf = 0; nf < 8; nf++)
#pragma unroll
                for (int j = 0; j < 4; j++) acc[mf][nf][j] = 0.f;
        run_half(bufB, wbuf, wbuf_addr, W2t + (size_t)nh * 128 * H_DIM, H_DIM, tid, acc);
#pragma unroll
        for (int mf = 0; mf < 2; mf++) {
            int r0 = wm * 32 + mf * 16 + g;
#pragma unroll
            for (int nf = 0; nf < 8; nf++) {
                int col = nh * 128 + wn * 64 + nf * 8 + tg * 2;
                float bb0 = __ldg(b2 + col), bb1 = __ldg(b2 + col + 1);
                float v0 = fmaxf(acc[mf][nf][0] + bb0, 0.f);
                float v1 = fmaxf(acc[mf][nf][1] + bb1, 0.f);
                float v2 = fmaxf(acc[mf][nf][2] + bb0, 0.f);
                float v3 = fmaxf(acc[mf][nf][3] + bb1, 0.f);
                int cu = col >> 1;
                bufA[r0 * AB_STRIDE + cu]       = u32_of_h2(__floats2half2_rn(v0, v1));
                bufA[(r0 + 8) * AB_STRIDE + cu] = u32_of_h2(__floats2half2_rn(v2, v3));
            }
        }
    }
    __syncthreads();

    // Stage 3: kv = h2 @ W3 + b3; halves 0,1 -> k (dot with q -> logits),
    //          halves 2,3 -> v (fp32 to gmem). bufB (h1, dead) reused for q gather.
    float* qb = (float*)bufB;
#pragma unroll
    for (int nh = 0; nh < 4; nh++) {
        __syncthreads();   // protect bufB (q gather) against previous half's dot reads
        if (nh < 2) {
            // gather q[seg[t]][nh*128 .. +128) as fp32 into qb
#pragma unroll
            for (int i = 0; i < 16; i++) {
                int idx = tid + i * 256;
                int row = idx >> 5, c16 = idx & 31;
                const float4 v = *reinterpret_cast<const float4*>(
                    q + (size_t)s_seg[row] * H_DIM + nh * 128 + c16 * 4);
                *reinterpret_cast<float4*>(qb + row * AB_STRIDE + c16 * 4) = v;
            }
        }
#pragma unroll
        for (int mf = 0; mf < 2; mf++)
#pragma unroll
            for (int nf = 0; nf < 8; nf++)
#pragma unroll
                for (int j = 0; j < 4; j++) acc[mf][nf][j] = 0.f;
        run_half(bufA, wbuf, wbuf_addr, W3t + (size_t)nh * 128 * H_DIM, H_DIM, tid, acc);

        if (nh < 2) {
            // k-half: partial dot with gathered q, reduce over tg, accumulate in smem
#pragma unroll
            for (int mf = 0; mf < 2; mf++) {
                int rA = wm * 32 + mf * 16 + g;
                int rB = rA + 8;
                float pA = 0.f, pB = 0.f;
#pragma unroll
                for (int nf = 0; nf < 8; nf++) {
                    int cq = wn * 64 + nf * 8 + tg * 2;
                    int col = nh * 128 + cq;
                    float bb0 = __ldg(b3 + col), bb1 = __ldg(b3 + col + 1);
                    float q0A = qb[rA * AB_STRIDE + cq], q1A = qb[rA * AB_STRIDE + cq + 1];
                    float q0B = qb[rB * AB_STRIDE + cq], q1B = qb[rB * AB_STRIDE + cq + 1];
                    pA = fmaf(acc[mf][nf][0] + bb0, q0A, pA);
                    pA = fmaf(acc[mf][nf][1] + bb1, q1A, pA);
                    pB = fmaf(acc[mf][nf][2] + bb0, q0B, pB);
                    pB = fmaf(acc[mf][nf][3] + bb1, q1B, pB);
                }
                pA += __shfl_xor_sync(0xffffffffu, pA, 1);
                pA += __shfl_xor_sync(0xffffffffu, pA, 2);
                pB += __shfl_xor_sync(0xffffffffu, pB, 1);
                pB += __shfl_xor_sync(0xffffffffu, pB, 2);
                if (tg == 0) {
                    atomicAdd(s_logit + rA, pA);
                    atomicAdd(s_logit + rB, pB);
                }
            }
        } else {
            // v-half: bias + fp32 store
#pragma unroll
            for (int mf = 0; mf < 2; mf++) {
                size_t r0 = t0 + wm * 32 + mf * 16 + g;
#pragma unroll
                for (int nf = 0; nf < 8; nf++) {
                    int col = nh * 128 + wn * 64 + nf * 8 + tg * 2;     // 256..511
                    float bb0 = __ldg(b3 + col), bb1 = __ldg(b3 + col + 1);
                    int vc = col - 256;
                    *reinterpret_cast<float2*>(v_out + r0 * H_DIM + vc) =
                        make_float2(acc[mf][nf][0] + bb0, acc[mf][nf][1] + bb1);
                    *reinterpret_cast<float2*>(v_out + (r0 + 8) * H_DIM + vc) =
                        make_float2(acc[mf][nf][2] + bb0, acc[mf][nf][3] + bb1);
                }
            }
        }
    }
    __syncthreads();
    if (tid < 128) logits[t0 + tid] = s_logit[tid] * 0.0625f;   // 1/sqrt(256)
}

// ---------------------------------------------------------------------------
// q GEMM (round-4 kernel, fp32 out): C[M,N] = A @ Wt^T + bias
// ---------------------------------------------------------------------------
#define ST_U 20
#define STAGE_U32 (2 * 128 * ST_U)

__global__ __launch_bounds__(256, 2) void gemm_q(
    const __half* __restrict__ A, const __half* __restrict__ Wt,
    const float* __restrict__ bias, float* __restrict__ Cf,
    int M, int N, int K)
{
    __shared__ uint32_t sm[2 * STAGE_U32];
    const uint32_t sb = smem_u32(sm);

    const int tid = threadIdx.x;
    const int wid = tid >> 5, lane = tid & 31;
    const int g = lane >> 2, tg = lane & 3;
    const int wm = wid >> 1, wn = wid & 1;

    const size_t m0 = (size_t)blockIdx.y * 128;
    const size_t n0 = (size_t)blockIdx.x * 128;
    const __half* Ablk = A + m0 * K;
    const __half* Bblk = Wt + n0 * K;

    auto load_stage = [&](int s, int kblk) {
        const __half* Asrc = Ablk + kblk * 32;
        const __half* Bsrc = Bblk + kblk * 32;
        uint32_t abase = sb + (uint32_t)(s * STAGE_U32) * 4u;
        uint32_t bbase = abase + 128 * ST_U * 4u;
#pragma unroll
        for (int i = 0; i < 2; i++) {
            int idx = tid + i * 256;
            int row = idx >> 2, k8 = idx & 3;
            CP_ASYNC16(abase + (uint32_t)(row * 80 + k8 * 16), Asrc + (size_t)row * K + k8 * 8);
            CP_ASYNC16(bbase + (uint32_t)(row * 80 + k8 * 16), Bsrc + (size_t)row * K + k8 * 8);
        }
        CP_COMMIT();
    };

    float acc[2][8][4];
#pragma unroll
    for (int mf = 0; mf < 2; mf++)
#pragma unroll
        for (int nf = 0; nf < 8; nf++)
#pragma unroll
            for (int j = 0; j < 4; j++) acc[mf][nf][j] = 0.f;

    const int nk = K >> 5;
    load_stage(0, 0);
    for (int c = 0; c < nk; c++) {
        if (c + 1 < nk) { load_stage((c + 1) & 1, c + 1); CP_WAIT1(); }
        else            { CP_WAIT0(); }
        __syncthreads();
        const uint32_t* As = sm + (c & 1) * STAGE_U32;
        const uint32_t* Bs = As + 128 * ST_U;
#pragma unroll
        for (int ks = 0; ks < 2; ks++) {
            uint32_t a[2][4], b[8][2];
#pragma unroll
            for (int mf = 0; mf < 2; mf++) {
                int r = wm * 32 + mf * 16 + g;
                int kb = ks * 8 + tg;
                a[mf][0] = As[r * ST_U + kb];
                a[mf][1] = As[(r + 8) * ST_U + kb];
                a[mf][2] = As[r * ST_U + kb + 4];
                a[mf][3] = As[(r + 8) * ST_U + kb + 4];
            }
#pragma unroll
            for (int nf = 0; nf < 8; nf++) {
                int n = wn * 64 + nf * 8 + g;
                int kb = ks * 8 + tg;
                b[nf][0] = Bs[n * ST_U + kb];
                b[nf][1] = Bs[n * ST_U + kb + 4];
            }
#pragma unroll
            for (int mf = 0; mf < 2; mf++)
#pragma unroll
                for (int nf = 0; nf < 8; nf++)
                    mma_fp16(acc[mf][nf], a[mf], b[nf]);
        }
        __syncthreads();
    }
#pragma unroll
    for (int mf = 0; mf < 2; mf++) {
        size_t row0 = m0 + wm * 32 + mf * 16 + g;
#pragma unroll
        for (int nf = 0; nf < 8; nf++) {
            int col = (int)n0 + wn * 64 + nf * 8 + tg * 2;
            float b0 = bias[col], b1 = bias[col + 1];
            *reinterpret_cast<float2*>(Cf + row0 * N + col) =
                make_float2(acc[mf][nf][0] + b0, acc[mf][nf][1] + b1);
            *reinterpret_cast<float2*>(Cf + (row0 + 8) * N + col) =
                make_float2(acc[mf][nf][2] + b0, acc[mf][nf][3] + b1);
        }
    }
}

// ---------------------------------------------------------------------------
// Prep kernels
// ---------------------------------------------------------------------------
__global__ void cvt_fp16(const float* __restrict__ in, __half* __restrict__ out, int n4) {
    int i = blockIdx.x * 256 + threadIdx.x;
    if (i < n4) {
        float4 v = reinterpret_cast<const float4*>(in)[i];
        reinterpret_cast<__half2*>(out)[i * 2]     = __floats2half2_rn(v.x, v.y);
        reinterpret_cast<__half2*>(out)[i * 2 + 1] = __floats2half2_rn(v.z, v.w);
    }
}

__global__ void transpose_cvt(const float* __restrict__ W, __half* __restrict__ Wt, int K, int N) {
    int i = blockIdx.x * 256 + threadIdx.x;
    if (i < K * N) {
        int k = i / N, n = i - k * N;
        Wt[(size_t)n * K + k] = __float2half_rn(W[i]);
    }
}

__global__ void segstart_kernel(const int* __restrict__ seg, int T, int B)
{
    int t = blockIdx.x * 256 + threadIdx.x;
    if (t == 0) { g_segstart[seg[0]] = 0; g_segstart[B] = T; }
    if (t > 0 && t < T) {
        int s = seg[t];
        if (s != seg[t - 1]) g_segstart[s] = t;
    }
}

// Per-segment softmax + weighted value sum. One 256-thread block per segment.
__global__ __launch_bounds__(256) void segreduce_kernel(
    float* __restrict__ emb, float* __restrict__ wout)
{
    const int s = blockIdx.x;
    const int s0 = g_segstart[s];
    const int s1 = g_segstart[s + 1];
    const int tid = threadIdx.x;

    __shared__ float red[8];
    __shared__ float bcast;

    float m = -INFINITY;
    for (int t = s0 + tid; t < s1; t += 256) m = fmaxf(m, g_logits[t]);
#pragma unroll
    for (int o = 16; o; o >>= 1) m = fmaxf(m, __shfl_xor_sync(0xffffffffu, m, o));
    if ((tid & 31) == 0) red[tid >> 5] = m;
    __syncthreads();
    if (tid == 0) {
        float mm = red[0];
#pragma unroll
        for (int i = 1; i < 8; i++) mm = fmaxf(mm, red[i]);
        bcast = mm;
    }
    __syncthreads();
    m = bcast;
    __syncthreads();

    float z = 0.f;
    for (int t = s0 + tid; t < s1; t += 256) z += __expf(g_logits[t] - m);
#pragma unroll
    for (int o = 16; o; o >>= 1) z += __shfl_xor_sync(0xffffffffu, z, o);
    if ((tid & 31) == 0) red[tid >> 5] = z;
    __syncthreads();
    if (tid == 0) {
        float zz = 0.f;
#pragma unroll
        for (int i = 0; i < 8; i++) zz += red[i];
        bcast = zz;
    }
    __syncthreads();
    const float inv = 1.f / bcast;
    __syncthreads();

    for (int t = s0 + tid; t < s1; t += 256) wout[t] = __expf(g_logits[t] - m) * inv;
    __syncthreads();

    float acc = 0.f;
    for (int t = s0; t < s1; t++) {
        float w = wout[t];
        acc = fmaf(w, g_v[(size_t)t * H_DIM + tid], acc);
    }
    emb[(size_t)s * H_DIM + tid] = acc;
}

// ---------------------------------------------------------------------------
// Launch
// ---------------------------------------------------------------------------
extern "C" void kernel_launch(void* const* d_in, const int* in_sizes, int n_in,
                              void* d_out, int out_size)
{
    const float* objects = (const float*)d_in[0];
    const float* context = (const float*)d_in[1];
    const int*   seg     = (const int*)  d_in[2];
    const float* W1 = (const float*)d_in[3];
    const float* b1 = (const float*)d_in[4];
    const float* W2 = (const float*)d_in[5];
    const float* b2 = (const float*)d_in[6];
    const float* W3 = (const float*)d_in[7];
    const float* b3 = (const float*)d_in[8];
    const float* Wq = (const float*)d_in[9];
    const float* bq = (const float*)d_in[10];

    const int T = in_sizes[2];                 // 262144
    const int B = in_sizes[1] / C_DIM;         // 4096

    float* out = (float*)d_out;
    float* emb_out = out;
    float* w_out   = out + (size_t)B * H_DIM;

    __half *p_ctxh, *p_w1, *p_w2, *p_w3, *p_wq;
    float *p_v, *p_q, *p_logits;
    cudaGetSymbolAddress((void**)&p_ctxh, g_ctxh);
    cudaGetSymbolAddress((void**)&p_v,  g_v);
    cudaGetSymbolAddress((void**)&p_q,  g_q);
    cudaGetSymbolAddress((void**)&p_w1, g_Wt1);
    cudaGetSymbolAddress((void**)&p_w2, g_Wt2);
    cudaGetSymbolAddress((void**)&p_w3, g_Wt3);
    cudaGetSymbolAddress((void**)&p_wq, g_Wtq);
    cudaGetSymbolAddress((void**)&p_logits, g_logits);

    cudaFuncSetAttribute(fused_mlp, cudaFuncAttributeMaxDynamicSharedMemorySize,
                         SMEM_FUSED_BYTES);

    // Weight prep + context fp16
    transpose_cvt<<<(F_DIM * H_DIM + 255) / 256, 256>>>(W1, p_w1, F_DIM, H_DIM);
    transpose_cvt<<<(H_DIM * H_DIM + 255) / 256, 256>>>(W2, p_w2, H_DIM, H_DIM);
    transpose_cvt<<<(H_DIM * KV_DIM + 255) / 256, 256>>>(W3, p_w3, H_DIM, KV_DIM);
    transpose_cvt<<<(C_DIM * H_DIM + 255) / 256, 256>>>(Wq, p_wq, C_DIM, H_DIM);
    cvt_fp16<<<(B * C_DIM / 4 + 255) / 256, 256>>>(context, p_ctxh, B * C_DIM / 4);

    // q = context @ Wq + bq  [4096,512] -> [4096,256] fp32
    gemm_q<<<dim3(H_DIM / 128, B / 128), 256>>>(p_ctxh, p_wq, bq, p_q, B, H_DIM, C_DIM);

    segstart_kernel<<<(T + 255) / 256, 256>>>(seg, T, B);

    // Fused MLP + logits
    fused_mlp<<<T / 128, 256, SMEM_FUSED_BYTES>>>(
        objects, p_w1, b1, p_w2, b2, p_w3, b3, p_q, seg, p_v, p_logits);

    segreduce_kernel<<<B, 256>>>(emb_out, w_out);
}

// round 7
// speedup vs baseline: 1.4166x; 1.4166x over previous
#include <cuda_runtime.h>
#include <cuda_fp16.h>
#include <math.h>
#include <stdint.h>

// Problem shapes (fixed by the dataset)
#define T_MAX 262144
#define B_MAX 4096
#define F_DIM 128
#define H_DIM 256
#define C_DIM 512
#define KV_DIM 512

// ---------------------------------------------------------------------------
// Scratch (allocation-free rule: __device__ globals)
// ---------------------------------------------------------------------------
__device__ __half g_objh[(size_t)T_MAX * F_DIM];      // 64 MB
__device__ __half g_ctxh[(size_t)B_MAX * C_DIM];      // 4 MB
__device__ __half g_h1 [(size_t)T_MAX * H_DIM];       // 128 MB
__device__ __half g_h2 [(size_t)T_MAX * H_DIM];       // 128 MB
__device__ float  g_v  [(size_t)T_MAX * H_DIM];       // 256 MB (v half of kv)
__device__ float  g_q  [(size_t)B_MAX * H_DIM];       // 4 MB
__device__ float  g_lp [2 * (size_t)T_MAX];           // 2 MB logit partials
__device__ __half g_Wt1[H_DIM * F_DIM];               // W1^T [N][K] fp16
__device__ __half g_Wt2[H_DIM * H_DIM];
__device__ __half g_Wt3[KV_DIM * H_DIM];
__device__ __half g_Wtq[H_DIM * C_DIM];
__device__ int    g_segstart[B_MAX + 1];

// ---------------------------------------------------------------------------
// Helpers
// ---------------------------------------------------------------------------
__device__ __forceinline__ uint32_t smem_u32(const void* p) {
    uint32_t a;
    asm("{ .reg .u64 t; cvta.to.shared.u64 t, %1; cvt.u32.u64 %0, t; }" : "=r"(a) : "l"(p));
    return a;
}

#define CP_ASYNC16(dst, src) \
    asm volatile("cp.async.cg.shared.global [%0], [%1], 16;" :: "r"(dst), "l"(src) : "memory")
#define CP_COMMIT() asm volatile("cp.async.commit_group;" ::: "memory")
#define CP_WAIT0()  asm volatile("cp.async.wait_group 0;" ::: "memory")
#define CP_WAIT1()  asm volatile("cp.async.wait_group 1;" ::: "memory")

// mma.sync m16n8k16 fp16 -> fp32 accumulate
__device__ __forceinline__ void mma_fp16(float* c, const uint32_t* a, const uint32_t* b) {
    asm volatile(
        "mma.sync.aligned.m16n8k16.row.col.f32.f16.f16.f32 "
        "{%0,%1,%2,%3}, {%4,%5,%6,%7}, {%8,%9}, {%0,%1,%2,%3};"
        : "+f"(c[0]), "+f"(c[1]), "+f"(c[2]), "+f"(c[3])
        : "r"(a[0]), "r"(a[1]), "r"(a[2]), "r"(a[3]), "r"(b[0]), "r"(b[1]));
}

#define ST_U 20
#define STAGE_U32 (2 * 128 * ST_U)

// Shared mainloop: 128x128 tile, K in 32-half chunks, 2-stage cp.async.
__device__ __forceinline__ void gemm_mainloop(
    uint32_t* sm, uint32_t sb,
    const __half* __restrict__ Ablk, const __half* __restrict__ Bblk,
    int K, int tid, float acc[2][8][4])
{
    const int wid = tid >> 5, lane = tid & 31;
    const int g = lane >> 2, tg = lane & 3;
    const int wm = wid >> 1, wn = wid & 1;

    auto load_stage = [&](int s, int kblk) {
        const __half* Asrc = Ablk + kblk * 32;
        const __half* Bsrc = Bblk + kblk * 32;
        uint32_t abase = sb + (uint32_t)(s * STAGE_U32) * 4u;
        uint32_t bbase = abase + 128 * ST_U * 4u;
#pragma unroll
        for (int i = 0; i < 2; i++) {
            int idx = tid + i * 256;
            int row = idx >> 2, k8 = idx & 3;
            CP_ASYNC16(abase + (uint32_t)(row * 80 + k8 * 16), Asrc + (size_t)row * K + k8 * 8);
            CP_ASYNC16(bbase + (uint32_t)(row * 80 + k8 * 16), Bsrc + (size_t)row * K + k8 * 8);
        }
        CP_COMMIT();
    };

#pragma unroll
    for (int mf = 0; mf < 2; mf++)
#pragma unroll
        for (int nf = 0; nf < 8; nf++)
#pragma unroll
            for (int j = 0; j < 4; j++) acc[mf][nf][j] = 0.f;

    const int nk = K >> 5;
    load_stage(0, 0);
    for (int c = 0; c < nk; c++) {
        if (c + 1 < nk) { load_stage((c + 1) & 1, c + 1); CP_WAIT1(); }
        else            { CP_WAIT0(); }
        __syncthreads();
        const uint32_t* As = sm + (c & 1) * STAGE_U32;
        const uint32_t* Bs = As + 128 * ST_U;
#pragma unroll
        for (int ks = 0; ks < 2; ks++) {
            uint32_t a[2][4], b[8][2];
#pragma unroll
            for (int mf = 0; mf < 2; mf++) {
                int r = wm * 32 + mf * 16 + g;
                int kb = ks * 8 + tg;
                a[mf][0] = As[r * ST_U + kb];
                a[mf][1] = As[(r + 8) * ST_U + kb];
                a[mf][2] = As[r * ST_U + kb + 4];
                a[mf][3] = As[(r + 8) * ST_U + kb + 4];
            }
#pragma unroll
            for (int nf = 0; nf < 8; nf++) {
                int n = wn * 64 + nf * 8 + g;
                int kb = ks * 8 + tg;
                b[nf][0] = Bs[n * ST_U + kb];
                b[nf][1] = Bs[n * ST_U + kb + 4];
            }
#pragma unroll
            for (int mf = 0; mf < 2; mf++)
#pragma unroll
                for (int nf = 0; nf < 8; nf++)
                    mma_fp16(acc[mf][nf], a[mf], b[nf]);
        }
        __syncthreads();
    }
}

// ---------------------------------------------------------------------------
// Standard GEMM (static smem, 2 CTA/SM): MODE 0 = fp32 out, MODE 1 = fp16+relu
// ---------------------------------------------------------------------------
template <bool RELU, int MODE>
__global__ __launch_bounds__(256, 2) void gemm_std(
    const __half* __restrict__ A, const __half* __restrict__ Wt,
    const float* __restrict__ bias,
    float* __restrict__ Cf, __half* __restrict__ Ch,
    int M, int N, int K)
{
    __shared__ uint32_t sm[2 * STAGE_U32];
    const uint32_t sb = smem_u32(sm);
    const int tid = threadIdx.x;
    const int wid = tid >> 5, lane = tid & 31;
    const int g = lane >> 2, tg = lane & 3;
    const int wm = wid >> 1, wn = wid & 1;

    const size_t m0 = (size_t)blockIdx.y * 128;
    const size_t n0 = (size_t)blockIdx.x * 128;

    float acc[2][8][4];
    gemm_mainloop(sm, sb, A + m0 * K, Wt + n0 * K, K, tid, acc);

#pragma unroll
    for (int mf = 0; mf < 2; mf++) {
        size_t row0 = m0 + wm * 32 + mf * 16 + g;
#pragma unroll
        for (int nf = 0; nf < 8; nf++) {
            int col = (int)n0 + wn * 64 + nf * 8 + tg * 2;
            float b0 = bias[col], b1 = bias[col + 1];
            float v0 = acc[mf][nf][0] + b0;
            float v1 = acc[mf][nf][1] + b1;
            float v2 = acc[mf][nf][2] + b0;
            float v3 = acc[mf][nf][3] + b1;
            if (RELU) { v0 = fmaxf(v0, 0.f); v1 = fmaxf(v1, 0.f); v2 = fmaxf(v2, 0.f); v3 = fmaxf(v3, 0.f); }
            if (MODE == 0) {
                *reinterpret_cast<float2*>(Cf + row0 * N + col)       = make_float2(v0, v1);
                *reinterpret_cast<float2*>(Cf + (row0 + 8) * N + col) = make_float2(v2, v3);
            } else {
                *reinterpret_cast<__half2*>(Ch + row0 * N + col)       = __floats2half2_rn(v0, v1);
                *reinterpret_cast<__half2*>(Ch + (row0 + 8) * N + col) = __floats2half2_rn(v2, v3);
            }
        }
    }
}

// ---------------------------------------------------------------------------
// kv GEMM with fused logits: grid (4, T/128), K = 256.
// n0 < 256: k-half -> dot fp32 accumulators against gathered q -> logit partials
// n0 >= 256: v-half -> fp32 store
// Dynamic smem 67584 B: GEMM stages (40960 B) reused as q tile [128][132] fp32.
// ---------------------------------------------------------------------------
#define QB_STRIDE 132

__global__ __launch_bounds__(256, 2) void gemm_kv(
    const __half* __restrict__ A, const __half* __restrict__ Wt,
    const float* __restrict__ bias,
    float* __restrict__ v_out, float* __restrict__ lpart,
    const float* __restrict__ q, const int* __restrict__ seg, int M)
{
    extern __shared__ uint32_t dyn[];
    __shared__ int   s_seg[128];
    __shared__ float s_logit[128];
    const uint32_t sb = smem_u32(dyn);

    const int tid = threadIdx.x;
    const int wid = tid >> 5, lane = tid & 31;
    const int g = lane >> 2, tg = lane & 3;
    const int wm = wid >> 1, wn = wid & 1;

    const size_t t0 = (size_t)blockIdx.y * 128;
    const int n0 = blockIdx.x * 128;
    const bool is_k = (n0 < 256);

    if (tid < 128) {
        if (is_k) s_seg[tid] = seg[t0 + tid];
        s_logit[tid] = 0.f;
    }

    float acc[2][8][4];
    gemm_mainloop(dyn, sb, A + t0 * H_DIM, Wt + (size_t)n0 * H_DIM, H_DIM, tid, acc);

    if (is_k) {
        // Gather q slice [128 rows][128 cols] into reused smem
        float* qb = (float*)dyn;
#pragma unroll
        for (int i = 0; i < 16; i++) {
            int idx = tid + i * 256;
            int row = idx >> 5, c16 = idx & 31;
            float4 v = *reinterpret_cast<const float4*>(
                q + (size_t)s_seg[row] * H_DIM + n0 + c16 * 4);
            *reinterpret_cast<float4*>(qb + row * QB_STRIDE + c16 * 4) = v;
        }
        __syncthreads();

#pragma unroll
        for (int mf = 0; mf < 2; mf++) {
            int rA = wm * 32 + mf * 16 + g;
            int rB = rA + 8;
            float pA = 0.f, pB = 0.f;
#pragma unroll
            for (int nf = 0; nf < 8; nf++) {
                int cq = wn * 64 + nf * 8 + tg * 2;
                int col = n0 + cq;
                float bb0 = __ldg(bias + col), bb1 = __ldg(bias + col + 1);
                float q0A = qb[rA * QB_STRIDE + cq], q1A = qb[rA * QB_STRIDE + cq + 1];
                float q0B = qb[rB * QB_STRIDE + cq], q1B = qb[rB * QB_STRIDE + cq + 1];
                pA = fmaf(acc[mf][nf][0] + bb0, q0A, pA);
                pA = fmaf(acc[mf][nf][1] + bb1, q1A, pA);
                pB = fmaf(acc[mf][nf][2] + bb0, q0B, pB);
                pB = fmaf(acc[mf][nf][3] + bb1, q1B, pB);
            }
            pA += __shfl_xor_sync(0xffffffffu, pA, 1);
            pA += __shfl_xor_sync(0xffffffffu, pA, 2);
            pB += __shfl_xor_sync(0xffffffffu, pB, 1);
            pB += __shfl_xor_sync(0xffffffffu, pB, 2);
            if (tg == 0) {
                atomicAdd(s_logit + rA, pA);
                atomicAdd(s_logit + rB, pB);
            }
        }
        __syncthreads();
        if (tid < 128)
            lpart[(size_t)blockIdx.x * M + t0 + tid] = s_logit[tid] * 0.0625f;
    } else {
#pragma unroll
        for (int mf = 0; mf < 2; mf++) {
            size_t r0 = t0 + wm * 32 + mf * 16 + g;
#pragma unroll
            for (int nf = 0; nf < 8; nf++) {
                int col = n0 + wn * 64 + nf * 8 + tg * 2;
                float bb0 = __ldg(bias + col), bb1 = __ldg(bias + col + 1);
                int vc = col - 256;
                *reinterpret_cast<float2*>(v_out + r0 * H_DIM + vc) =
                    make_float2(acc[0][0][0] * 0.f + acc[mf][nf][0] + bb0, acc[mf][nf][1] + bb1);
                *reinterpret_cast<float2*>(v_out + (r0 + 8) * H_DIM + vc) =
                    make_float2(acc[mf][nf][2] + bb0, acc[mf][nf][3] + bb1);
            }
        }
    }
}

// ---------------------------------------------------------------------------
// Prep kernels
// ---------------------------------------------------------------------------
__global__ void cvt_fp16(const float* __restrict__ in, __half* __restrict__ out, int n4) {
    int i = blockIdx.x * 256 + threadIdx.x;
    if (i < n4) {
        float4 v = reinterpret_cast<const float4*>(in)[i];
        reinterpret_cast<__half2*>(out)[i * 2]     = __floats2half2_rn(v.x, v.y);
        reinterpret_cast<__half2*>(out)[i * 2 + 1] = __floats2half2_rn(v.z, v.w);
    }
}

__global__ void transpose_cvt(const float* __restrict__ W, __half* __restrict__ Wt, int K, int N) {
    int i = blockIdx.x * 256 + threadIdx.x;
    if (i < K * N) {
        int k = i / N, n = i - k * N;
        Wt[(size_t)n * K + k] = __float2half_rn(W[i]);
    }
}

__global__ void segstart_kernel(const int* __restrict__ seg, int T, int B)
{
    int t = blockIdx.x * 256 + threadIdx.x;
    if (t == 0) { g_segstart[seg[0]] = 0; g_segstart[B] = T; }
    if (t > 0 && t < T) {
        int s = seg[t];
        if (s != seg[t - 1]) g_segstart[s] = t;
    }
}

// Per-segment softmax + weighted value sum. One 256-thread block per segment.
__global__ __launch_bounds__(256) void segreduce_kernel(
    const float* __restrict__ lp0, const float* __restrict__ lp1,
    float* __restrict__ emb, float* __restrict__ wout)
{
    const int s = blockIdx.x;
    const int s0 = g_segstart[s];
    const int s1 = g_segstart[s + 1];
    const int tid = threadIdx.x;

    __shared__ float red[8];
    __shared__ float bcast;

    float m = -INFINITY;
    for (int t = s0 + tid; t < s1; t += 256) m = fmaxf(m, lp0[t] + lp1[t]);
#pragma unroll
    for (int o = 16; o; o >>= 1) m = fmaxf(m, __shfl_xor_sync(0xffffffffu, m, o));
    if ((tid & 31) == 0) red[tid >> 5] = m;
    __syncthreads();
    if (tid == 0) {
        float mm = red[0];
#pragma unroll
        for (int i = 1; i < 8; i++) mm = fmaxf(mm, red[i]);
        bcast = mm;
    }
    __syncthreads();
    m = bcast;
    __syncthreads();

    float z = 0.f;
    for (int t = s0 + tid; t < s1; t += 256) z += __expf(lp0[t] + lp1[t] - m);
#pragma unroll
    for (int o = 16; o; o >>= 1) z += __shfl_xor_sync(0xffffffffu, z, o);
    if ((tid & 31) == 0) red[tid >> 5] = z;
    __syncthreads();
    if (tid == 0) {
        float zz = 0.f;
#pragma unroll
        for (int i = 0; i < 8; i++) zz += red[i];
        bcast = zz;
    }
    __syncthreads();
    const float inv = 1.f / bcast;
    __syncthreads();

    for (int t = s0 + tid; t < s1; t += 256) wout[t] = __expf(lp0[t] + lp1[t] - m) * inv;
    __syncthreads();

    float acc = 0.f;
    for (int t = s0; t < s1; t++) {
        float w = wout[t];
        acc = fmaf(w, g_v[(size_t)t * H_DIM + tid], acc);
    }
    emb[(size_t)s * H_DIM + tid] = acc;
}

// ---------------------------------------------------------------------------
// Launch
// ---------------------------------------------------------------------------
extern "C" void kernel_launch(void* const* d_in, const int* in_sizes, int n_in,
                              void* d_out, int out_size)
{
    const float* objects = (const float*)d_in[0];
    const float* context = (const float*)d_in[1];
    const int*   seg     = (const int*)  d_in[2];
    const float* W1 = (const float*)d_in[3];
    const float* b1 = (const float*)d_in[4];
    const float* W2 = (const float*)d_in[5];
    const float* b2 = (const float*)d_in[6];
    const float* W3 = (const float*)d_in[7];
    const float* b3 = (const float*)d_in[8];
    const float* Wq = (const float*)d_in[9];
    const float* bq = (const float*)d_in[10];

    const int T = in_sizes[2];                 // 262144
    const int B = in_sizes[1] / C_DIM;         // 4096

    float* out = (float*)d_out;
    float* emb_out = out;
    float* w_out   = out + (size_t)B * H_DIM;

    __half *p_objh, *p_ctxh, *p_h1, *p_h2, *p_w1, *p_w2, *p_w3, *p_wq;
    float *p_v, *p_q, *p_lp;
    cudaGetSymbolAddress((void**)&p_objh, g_objh);
    cudaGetSymbolAddress((void**)&p_ctxh, g_ctxh);
    cudaGetSymbolAddress((void**)&p_h1, g_h1);
    cudaGetSymbolAddress((void**)&p_h2, g_h2);
    cudaGetSymbolAddress((void**)&p_v,  g_v);
    cudaGetSymbolAddress((void**)&p_q,  g_q);
    cudaGetSymbolAddress((void**)&p_lp, g_lp);
    cudaGetSymbolAddress((void**)&p_w1, g_Wt1);
    cudaGetSymbolAddress((void**)&p_w2, g_Wt2);
    cudaGetSymbolAddress((void**)&p_w3, g_Wt3);
    cudaGetSymbolAddress((void**)&p_wq, g_Wtq);

    cudaFuncSetAttribute(gemm_kv, cudaFuncAttributeMaxDynamicSharedMemorySize,
                         128 * QB_STRIDE * 4);

    // Convert inputs to fp16
    cvt_fp16<<<(T * F_DIM / 4 + 255) / 256, 256>>>(objects, p_objh, T * F_DIM / 4);
    cvt_fp16<<<(B * C_DIM / 4 + 255) / 256, 256>>>(context, p_ctxh, B * C_DIM / 4);
    // Transpose + convert weights to K-major [N][K] fp16
    transpose_cvt<<<(F_DIM * H_DIM + 255) / 256, 256>>>(W1, p_w1, F_DIM, H_DIM);
    transpose_cvt<<<(H_DIM * H_DIM + 255) / 256, 256>>>(W2, p_w2, H_DIM, H_DIM);
    transpose_cvt<<<(H_DIM * KV_DIM + 255) / 256, 256>>>(W3, p_w3, H_DIM, KV_DIM);
    transpose_cvt<<<(C_DIM * H_DIM + 255) / 256, 256>>>(Wq, p_wq, C_DIM, H_DIM);

    segstart_kernel<<<(T + 255) / 256, 256>>>(seg, T, B);

    // q = context @ Wq + bq  [4096,512]->[4096,256] fp32 out
    gemm_std<false, 0><<<dim3(H_DIM / 128, B / 128), 256>>>(
        p_ctxh, p_wq, bq, p_q, nullptr, B, H_DIM, C_DIM);
    // h1 = relu(objects @ W1 + b1)  fp16 out
    gemm_std<true, 1><<<dim3(H_DIM / 128, T / 128), 256>>>(
        p_objh, p_w1, b1, nullptr, p_h1, T, H_DIM, F_DIM);
    // h2 = relu(h1 @ W2 + b2)  fp16 out
    gemm_std<true, 1><<<dim3(H_DIM / 128, T / 128), 256>>>(
        p_h1, p_w2, b2, nullptr, p_h2, T, H_DIM, H_DIM);
    // kv: k-halves -> fused logit partials, v-halves -> g_v
    gemm_kv<<<dim3(KV_DIM / 128, T / 128), 256, 128 * QB_STRIDE * 4>>>(
        p_h2, p_w3, b3, p_v, p_lp, p_q, seg, T);

    segreduce_kernel<<<B, 256>>>(p_lp, p_lp + T, emb_out, w_out);
}

// round 8
// speedup vs baseline: 1.4953x; 1.0555x over previous
#include <cuda_runtime.h>
#include <cuda_fp16.h>
#include <math.h>
#include <stdint.h>

// Problem shapes (fixed by the dataset)
#define T_MAX 262144
#define B_MAX 4096
#define F_DIM 128
#define H_DIM 256
#define C_DIM 512
#define KV_DIM 512

// ---------------------------------------------------------------------------
// Scratch (allocation-free rule: __device__ globals)
// ---------------------------------------------------------------------------
__device__ __half g_objh[(size_t)T_MAX * F_DIM];      // 64 MB
__device__ __half g_ctxh[(size_t)B_MAX * C_DIM];      // 4 MB
__device__ __half g_h1 [(size_t)T_MAX * H_DIM];       // 128 MB
__device__ __half g_h2 [(size_t)T_MAX * H_DIM];       // 128 MB
__device__ __half g_vh [(size_t)T_MAX * H_DIM];       // 128 MB (v half of kv, fp16)
__device__ float  g_q  [(size_t)B_MAX * H_DIM];       // 4 MB
__device__ float  g_lp [2 * (size_t)T_MAX];           // 2 MB logit partials
__device__ __half g_Wt1[H_DIM * F_DIM];               // W1^T [N][K] fp16
__device__ __half g_Wt2[H_DIM * H_DIM];
__device__ __half g_Wt3[KV_DIM * H_DIM];
__device__ __half g_Wtq[H_DIM * C_DIM];
__device__ int    g_segstart[B_MAX + 1];

// ---------------------------------------------------------------------------
// Helpers
// ---------------------------------------------------------------------------
__device__ __forceinline__ uint32_t smem_u32(const void* p) {
    uint32_t a;
    asm("{ .reg .u64 t; cvta.to.shared.u64 t, %1; cvt.u32.u64 %0, t; }" : "=r"(a) : "l"(p));
    return a;
}

#define CP_ASYNC16(dst, src) \
    asm volatile("cp.async.cg.shared.global [%0], [%1], 16;" :: "r"(dst), "l"(src) : "memory")
#define CP_COMMIT() asm volatile("cp.async.commit_group;" ::: "memory")
#define CP_WAIT0()  asm volatile("cp.async.wait_group 0;" ::: "memory")
#define CP_WAIT1()  asm volatile("cp.async.wait_group 1;" ::: "memory")

#define LDSM_X4(r0, r1, r2, r3, addr) \
    asm volatile("ldmatrix.sync.aligned.m8n8.x4.shared.b16 {%0,%1,%2,%3}, [%4];" \
        : "=r"(r0), "=r"(r1), "=r"(r2), "=r"(r3) : "r"(addr))

// mma.sync m16n8k16 fp16 -> fp32 accumulate
__device__ __forceinline__ void mma_fp16(float* c, const uint32_t* a, const uint32_t* b) {
    asm volatile(
        "mma.sync.aligned.m16n8k16.row.col.f32.f16.f16.f32 "
        "{%0,%1,%2,%3}, {%4,%5,%6,%7}, {%8,%9}, {%0,%1,%2,%3};"
        : "+f"(c[0]), "+f"(c[1]), "+f"(c[2]), "+f"(c[3])
        : "r"(a[0]), "r"(a[1]), "r"(a[2]), "r"(a[3]), "r"(b[0]), "r"(b[1]));
}

// Stage layout: A rows 0..127 (stride 80 B) then B rows 0..127 (stride 80 B)
#define ROW_B 80
#define STAGE_BYTES (2 * 128 * ROW_B)        // 20480 B
#define NSTAGE 3
#define GEMM_SMEM (NSTAGE * STAGE_BYTES)     // 61440 B

// ---------------------------------------------------------------------------
// Shared mainloop: 128x128 tile, BK=32, 3-stage cp.async, ldmatrix fragments.
// ---------------------------------------------------------------------------
__device__ __forceinline__ void gemm_mainloop(
    uint32_t sb,                             // smem byte address of stage 0
    const __half* __restrict__ Ablk, const __half* __restrict__ Bblk,
    int K, int tid, float acc[2][8][4])
{
    const int wid = tid >> 5, lane = tid & 31;
    const int wm = wid >> 1, wn = wid & 1;
    const int lm_r = lane & 15;              // row within 16-row block
    const int lm_k = (lane >> 4) * 16;       // +0 / +16 B (k-halves)

    auto load_stage = [&](int s, int kblk) {
        const __half* Asrc = Ablk + kblk * 32;
        const __half* Bsrc = Bblk + kblk * 32;
        uint32_t abase = sb + (uint32_t)s * STAGE_BYTES;
        uint32_t bbase = abase + 128 * ROW_B;
#pragma unroll
        for (int i = 0; i < 2; i++) {
            int idx = tid + i * 256;
            int row = idx >> 2, k8 = idx & 3;
            CP_ASYNC16(abase + (uint32_t)(row * ROW_B + k8 * 16), Asrc + (size_t)row * K + k8 * 8);
            CP_ASYNC16(bbase + (uint32_t)(row * ROW_B + k8 * 16), Bsrc + (size_t)row * K + k8 * 8);
        }
        CP_COMMIT();
    };

#pragma unroll
    for (int mf = 0; mf < 2; mf++)
#pragma unroll
        for (int nf = 0; nf < 8; nf++)
#pragma unroll
            for (int j = 0; j < 4; j++) acc[mf][nf][j] = 0.f;

    const int nk = K >> 5;
    load_stage(0, 0);
    load_stage(1, 1);

    for (int c = 0; c < nk; c++) {
        if (c + 1 < nk) CP_WAIT1(); else CP_WAIT0();
        __syncthreads();
        if (c + 2 < nk) load_stage((c + 2) % NSTAGE, c + 2);

        const uint32_t Ab = sb + (uint32_t)(c % NSTAGE) * STAGE_BYTES;
        const uint32_t Bb = Ab + 128 * ROW_B;

#pragma unroll
        for (int ks = 0; ks < 2; ks++) {
            uint32_t a[2][4], b[8][2];
#pragma unroll
            for (int mf = 0; mf < 2; mf++) {
                uint32_t addr = Ab + (uint32_t)((wm * 32 + mf * 16 + lm_r) * ROW_B + ks * 32) + lm_k;
                LDSM_X4(a[mf][0], a[mf][1], a[mf][2], a[mf][3], addr);
            }
#pragma unroll
            for (int p = 0; p < 4; p++) {
                uint32_t addr = Bb + (uint32_t)((wn * 64 + p * 16 + lm_r) * ROW_B + ks * 32) + lm_k;
                LDSM_X4(b[2 * p][0], b[2 * p + 1][0], b[2 * p][1], b[2 * p + 1][1], addr);
            }
#pragma unroll
            for (int mf = 0; mf < 2; mf++)
#pragma unroll
                for (int nf = 0; nf < 8; nf++)
                    mma_fp16(acc[mf][nf], a[mf], b[nf]);
        }
    }
    __syncthreads();   // stages reused by caller epilogues / next use
}

// ---------------------------------------------------------------------------
// Standard GEMM (dynamic smem, 2 CTA/SM): MODE 0 = fp32 out, MODE 1 = fp16 out
// ---------------------------------------------------------------------------
template <bool RELU, int MODE>
__global__ __launch_bounds__(256, 2) void gemm_std(
    const __half* __restrict__ A, const __half* __restrict__ Wt,
    const float* __restrict__ bias,
    float* __restrict__ Cf, __half* __restrict__ Ch,
    int M, int N, int K)
{
    extern __shared__ uint32_t dyn[];
    const uint32_t sb = smem_u32(dyn);
    const int tid = threadIdx.x;
    const int wid = tid >> 5, lane = tid & 31;
    const int g = lane >> 2, tg = lane & 3;
    const int wm = wid >> 1, wn = wid & 1;

    const size_t m0 = (size_t)blockIdx.y * 128;
    const size_t n0 = (size_t)blockIdx.x * 128;

    float acc[2][8][4];
    gemm_mainloop(sb, A + m0 * K, Wt + n0 * K, K, tid, acc);

#pragma unroll
    for (int mf = 0; mf < 2; mf++) {
        size_t row0 = m0 + wm * 32 + mf * 16 + g;
#pragma unroll
        for (int nf = 0; nf < 8; nf++) {
            int col = (int)n0 + wn * 64 + nf * 8 + tg * 2;
            float b0 = bias[col], b1 = bias[col + 1];
            float v0 = acc[mf][nf][0] + b0;
            float v1 = acc[mf][nf][1] + b1;
            float v2 = acc[mf][nf][2] + b0;
            float v3 = acc[mf][nf][3] + b1;
            if (RELU) { v0 = fmaxf(v0, 0.f); v1 = fmaxf(v1, 0.f); v2 = fmaxf(v2, 0.f); v3 = fmaxf(v3, 0.f); }
            if (MODE == 0) {
                *reinterpret_cast<float2*>(Cf + row0 * N + col)       = make_float2(v0, v1);
                *reinterpret_cast<float2*>(Cf + (row0 + 8) * N + col) = make_float2(v2, v3);
            } else {
                *reinterpret_cast<__half2*>(Ch + row0 * N + col)       = __floats2half2_rn(v0, v1);
                *reinterpret_cast<__half2*>(Ch + (row0 + 8) * N + col) = __floats2half2_rn(v2, v3);
            }
        }
    }
}

// ---------------------------------------------------------------------------
// kv GEMM with fused logits: grid (4, T/128), K = 256.
// n0 < 256: k-half -> dot fp32 accumulators against gathered q -> logit partials
// n0 >= 256: v-half -> fp16 store
// Dynamic smem 67584 B: GEMM stages (61440 B) reused as q tile [128][132] fp32.
// ---------------------------------------------------------------------------
#define QB_STRIDE 132
#define KV_SMEM (128 * QB_STRIDE * 4)        // 67584 > GEMM_SMEM

__global__ __launch_bounds__(256, 2) void gemm_kv(
    const __half* __restrict__ A, const __half* __restrict__ Wt,
    const float* __restrict__ bias,
    __half* __restrict__ v_out, float* __restrict__ lpart,
    const float* __restrict__ q, const int* __restrict__ seg, int M)
{
    extern __shared__ uint32_t dyn[];
    __shared__ int   s_seg[128];
    __shared__ float s_logit[128];
    const uint32_t sb = smem_u32(dyn);

    const int tid = threadIdx.x;
    const int wid = tid >> 5, lane = tid & 31;
    const int g = lane >> 2, tg = lane & 3;
    const int wm = wid >> 1, wn = wid & 1;

    const size_t t0 = (size_t)blockIdx.y * 128;
    const int n0 = blockIdx.x * 128;
    const bool is_k = (n0 < 256);

    if (tid < 128) {
        if (is_k) s_seg[tid] = seg[t0 + tid];
        s_logit[tid] = 0.f;
    }

    float acc[2][8][4];
    gemm_mainloop(sb, A + t0 * H_DIM, Wt + (size_t)n0 * H_DIM, H_DIM, tid, acc);

    if (is_k) {
        // Gather q slice [128 rows][128 cols] into reused smem
        float* qb = (float*)dyn;
#pragma unroll
        for (int i = 0; i < 16; i++) {
            int idx = tid + i * 256;
            int row = idx >> 5, c16 = idx & 31;
            float4 v = *reinterpret_cast<const float4*>(
                q + (size_t)s_seg[row] * H_DIM + n0 + c16 * 4);
            *reinterpret_cast<float4*>(qb + row * QB_STRIDE + c16 * 4) = v;
        }
        __syncthreads();

#pragma unroll
        for (int mf = 0; mf < 2; mf++) {
            int rA = wm * 32 + mf * 16 + g;
            int rB = rA + 8;
            float pA = 0.f, pB = 0.f;
#pragma unroll
            for (int nf = 0; nf < 8; nf++) {
                int cq = wn * 64 + nf * 8 + tg * 2;
                int col = n0 + cq;
                float bb0 = __ldg(bias + col), bb1 = __ldg(bias + col + 1);
                float q0A = qb[rA * QB_STRIDE + cq], q1A = qb[rA * QB_STRIDE + cq + 1];
                float q0B = qb[rB * QB_STRIDE + cq], q1B = qb[rB * QB_STRIDE + cq + 1];
                pA = fmaf(acc[mf][nf][0] + bb0, q0A, pA);
                pA = fmaf(acc[mf][nf][1] + bb1, q1A, pA);
                pB = fmaf(acc[mf][nf][2] + bb0, q0B, pB);
                pB = fmaf(acc[mf][nf][3] + bb1, q1B, pB);
            }
            pA += __shfl_xor_sync(0xffffffffu, pA, 1);
            pA += __shfl_xor_sync(0xffffffffu, pA, 2);
            pB += __shfl_xor_sync(0xffffffffu, pB, 1);
            pB += __shfl_xor_sync(0xffffffffu, pB, 2);
            if (tg == 0) {
                atomicAdd(s_logit + rA, pA);
                atomicAdd(s_logit + rB, pB);
            }
        }
        __syncthreads();
        if (tid < 128)
            lpart[(size_t)blockIdx.x * M + t0 + tid] = s_logit[tid] * 0.0625f;
    } else {
#pragma unroll
        for (int mf = 0; mf < 2; mf++) {
            size_t r0 = t0 + wm * 32 + mf * 16 + g;
#pragma unroll
            for (int nf = 0; nf < 8; nf++) {
                int col = n0 + wn * 64 + nf * 8 + tg * 2;
                float bb0 = __ldg(bias + col), bb1 = __ldg(bias + col + 1);
                int vc = col - 256;
                *reinterpret_cast<__half2*>(v_out + r0 * H_DIM + vc) =
                    __floats2half2_rn(acc[mf][nf][0] + bb0, acc[mf][nf][1] + bb1);
                *reinterpret_cast<__half2*>(v_out + (r0 + 8) * H_DIM + vc) =
                    __floats2half2_rn(acc[mf][nf][2] + bb0, acc[mf][nf][3] + bb1);
            }
        }
    }
}

// ---------------------------------------------------------------------------
// Prep kernels
// ---------------------------------------------------------------------------
__global__ void cvt_fp16(const float* __restrict__ in, __half* __restrict__ out, int n4) {
    int i = blockIdx.x * 256 + threadIdx.x;
    if (i < n4) {
        float4 v = reinterpret_cast<const float4*>(in)[i];
        reinterpret_cast<__half2*>(out)[i * 2]     = __floats2half2_rn(v.x, v.y);
        reinterpret_cast<__half2*>(out)[i * 2 + 1] = __floats2half2_rn(v.z, v.w);
    }
}

__global__ void transpose_cvt(const float* __restrict__ W, __half* __restrict__ Wt, int K, int N) {
    int i = blockIdx.x * 256 + threadIdx.x;
    if (i < K * N) {
        int k = i / N, n = i - k * N;
        Wt[(size_t)n * K + k] = __float2half_rn(W[i]);
    }
}

__global__ void segstart_kernel(const int* __restrict__ seg, int T, int B)
{
    int t = blockIdx.x * 256 + threadIdx.x;
    if (t == 0) { g_segstart[seg[0]] = 0; g_segstart[B] = T; }
    if (t > 0 && t < T) {
        int s = seg[t];
        if (s != seg[t - 1]) g_segstart[s] = t;
    }
}

// Per-segment softmax + weighted value sum. One 256-thread block per segment.
__global__ __launch_bounds__(256) void segreduce_kernel(
    const float* __restrict__ lp0, const float* __restrict__ lp1,
    float* __restrict__ emb, float* __restrict__ wout)
{
    const int s = blockIdx.x;
    const int s0 = g_segstart[s];
    const int s1 = g_segstart[s + 1];
    const int tid = threadIdx.x;

    __shared__ float red[8];
    __shared__ float bcast;

    float m = -INFINITY;
    for (int t = s0 + tid; t < s1; t += 256) m = fmaxf(m, lp0[t] + lp1[t]);
#pragma unroll
    for (int o = 16; o; o >>= 1) m = fmaxf(m, __shfl_xor_sync(0xffffffffu, m, o));
    if ((tid & 31) == 0) red[tid >> 5] = m;
    __syncthreads();
    if (tid == 0) {
        float mm = red[0];
#pragma unroll
        for (int i = 1; i < 8; i++) mm = fmaxf(mm, red[i]);
        bcast = mm;
    }
    __syncthreads();
    m = bcast;
    __syncthreads();

    float z = 0.f;
    for (int t = s0 + tid; t < s1; t += 256) z += __expf(lp0[t] + lp1[t] - m);
#pragma unroll
    for (int o = 16; o; o >>= 1) z += __shfl_xor_sync(0xffffffffu, z, o);
    if ((tid & 31) == 0) red[tid >> 5] = z;
    __syncthreads();
    if (tid == 0) {
        float zz = 0.f;
#pragma unroll
        for (int i = 0; i < 8; i++) zz += red[i];
        bcast = zz;
    }
    __syncthreads();
    const float inv = 1.f / bcast;
    __syncthreads();

    for (int t = s0 + tid; t < s1; t += 256) wout[t] = __expf(lp0[t] + lp1[t] - m) * inv;
    __syncthreads();

    float acc = 0.f;
    for (int t = s0; t < s1; t++) {
        float w = wout[t];
        acc = fmaf(w, __half2float(g_vh[(size_t)t * H_DIM + tid]), acc);
    }
    emb[(size_t)s * H_DIM + tid] = acc;
}

// ---------------------------------------------------------------------------
// Launch
// ---------------------------------------------------------------------------
extern "C" void kernel_launch(void* const* d_in, const int* in_sizes, int n_in,
                              void* d_out, int out_size)
{
    const float* objects = (const float*)d_in[0];
    const float* context = (const float*)d_in[1];
    const int*   seg     = (const int*)  d_in[2];
    const float* W1 = (const float*)d_in[3];
    const float* b1 = (const float*)d_in[4];
    const float* W2 = (const float*)d_in[5];
    const float* b2 = (const float*)d_in[6];
    const float* W3 = (const float*)d_in[7];
    const float* b3 = (const float*)d_in[8];
    const float* Wq = (const float*)d_in[9];
    const float* bq = (const float*)d_in[10];

    const int T = in_sizes[2];                 // 262144
    const int B = in_sizes[1] / C_DIM;         // 4096

    float* out = (float*)d_out;
    float* emb_out = out;
    float* w_out   = out + (size_t)B * H_DIM;

    __half *p_objh, *p_ctxh, *p_h1, *p_h2, *p_vh, *p_w1, *p_w2, *p_w3, *p_wq;
    float *p_q, *p_lp;
    cudaGetSymbolAddress((void**)&p_objh, g_objh);
    cudaGetSymbolAddress((void**)&p_ctxh, g_ctxh);
    cudaGetSymbolAddress((void**)&p_h1, g_h1);
    cudaGetSymbolAddress((void**)&p_h2, g_h2);
    cudaGetSymbolAddress((void**)&p_vh, g_vh);
    cudaGetSymbolAddress((void**)&p_q,  g_q);
    cudaGetSymbolAddress((void**)&p_lp, g_lp);
    cudaGetSymbolAddress((void**)&p_w1, g_Wt1);
    cudaGetSymbolAddress((void**)&p_w2, g_Wt2);
    cudaGetSymbolAddress((void**)&p_w3, g_Wt3);
    cudaGetSymbolAddress((void**)&p_wq, g_Wtq);

    cudaFuncSetAttribute(gemm_std<false, 0>, cudaFuncAttributeMaxDynamicSharedMemorySize, GEMM_SMEM);
    cudaFuncSetAttribute(gemm_std<true, 1>,  cudaFuncAttributeMaxDynamicSharedMemorySize, GEMM_SMEM);
    cudaFuncSetAttribute(gemm_kv, cudaFuncAttributeMaxDynamicSharedMemorySize, KV_SMEM);

    // Convert inputs to fp16
    cvt_fp16<<<(T * F_DIM / 4 + 255) / 256, 256>>>(objects, p_objh, T * F_DIM / 4);
    cvt_fp16<<<(B * C_DIM / 4 + 255) / 256, 256>>>(context, p_ctxh, B * C_DIM / 4);
    // Transpose + convert weights to K-major [N][K] fp16
    transpose_cvt<<<(F_DIM * H_DIM + 255) / 256, 256>>>(W1, p_w1, F_DIM, H_DIM);
    transpose_cvt<<<(H_DIM * H_DIM + 255) / 256, 256>>>(W2, p_w2, H_DIM, H_DIM);
    transpose_cvt<<<(H_DIM * KV_DIM + 255) / 256, 256>>>(W3, p_w3, H_DIM, KV_DIM);
    transpose_cvt<<<(C_DIM * H_DIM + 255) / 256, 256>>>(Wq, p_wq, C_DIM, H_DIM);

    segstart_kernel<<<(T + 255) / 256, 256>>>(seg, T, B);

    // q = context @ Wq + bq  [4096,512]->[4096,256] fp32 out
    gemm_std<false, 0><<<dim3(H_DIM / 128, B / 128), 256, GEMM_SMEM>>>(
        p_ctxh, p_wq, bq, p_q, nullptr, B, H_DIM, C_DIM);
    // h1 = relu(objects @ W1 + b1)  fp16 out
    gemm_std<true, 1><<<dim3(H_DIM / 128, T / 128), 256, GEMM_SMEM>>>(
        p_objh, p_w1, b1, nullptr, p_h1, T, H_DIM, F_DIM);
    // h2 = relu(h1 @ W2 + b2)  fp16 out
    gemm_std<true, 1><<<dim3(H_DIM / 128, T / 128), 256, GEMM_SMEM>>>(
        p_h1, p_w2, b2, nullptr, p_h2, T, H_DIM, H_DIM);
    // kv: k-halves -> fused logit partials, v-halves -> g_vh (fp16)
    gemm_kv<<<dim3(KV_DIM / 128, T / 128), 256, KV_SMEM>>>(
        p_h2, p_w3, b3, p_vh, p_lp, p_q, seg, T);

    segreduce_kernel<<<B, 256>>>(p_lp, p_lp + T, emb_out, w_out);
}

// round 9
// speedup vs baseline: 1.6506x; 1.1039x over previous
#include <cuda_runtime.h>
#include <cuda_fp16.h>
#include <math.h>
#include <stdint.h>

// Problem shapes (fixed by the dataset)
#define T_MAX 262144
#define B_MAX 4096
#define F_DIM 128
#define H_DIM 256
#define C_DIM 512
#define KV_DIM 512

// ---------------------------------------------------------------------------
// Scratch (allocation-free rule: __device__ globals)
// ---------------------------------------------------------------------------
__device__ __half g_objh[(size_t)T_MAX * F_DIM];      // 64 MB
__device__ __half g_ctxh[(size_t)B_MAX * C_DIM];      // 4 MB
__device__ __half g_h1 [(size_t)T_MAX * H_DIM];       // 128 MB
__device__ __half g_h2 [(size_t)T_MAX * H_DIM];       // 128 MB
__device__ __half g_vh [(size_t)T_MAX * H_DIM];       // 128 MB (v half of kv, fp16)
__device__ float  g_q  [(size_t)B_MAX * H_DIM];       // 4 MB
__device__ float  g_lp [2 * (size_t)T_MAX];           // 2 MB logit partials
__device__ __half g_Wt1[H_DIM * F_DIM];               // W1^T [N][K] fp16
__device__ __half g_Wt2[H_DIM * H_DIM];
__device__ __half g_Wt3[KV_DIM * H_DIM];
__device__ __half g_Wtq[H_DIM * C_DIM];
__device__ int    g_segstart[B_MAX + 1];

// ---------------------------------------------------------------------------
// Helpers
// ---------------------------------------------------------------------------
__device__ __forceinline__ uint32_t smem_u32(const void* p) {
    uint32_t a;
    asm("{ .reg .u64 t; cvta.to.shared.u64 t, %1; cvt.u32.u64 %0, t; }" : "=r"(a) : "l"(p));
    return a;
}

#define CP_ASYNC16(dst, src) \
    asm volatile("cp.async.cg.shared.global [%0], [%1], 16;" :: "r"(dst), "l"(src) : "memory")
#define CP_COMMIT() asm volatile("cp.async.commit_group;" ::: "memory")
#define CP_WAIT0()  asm volatile("cp.async.wait_group 0;" ::: "memory")
#define CP_WAIT1()  asm volatile("cp.async.wait_group 1;" ::: "memory")

#define LDSM_X4(r0, r1, r2, r3, addr) \
    asm volatile("ldmatrix.sync.aligned.m8n8.x4.shared.b16 {%0,%1,%2,%3}, [%4];" \
        : "=r"(r0), "=r"(r1), "=r"(r2), "=r"(r3) : "r"(addr))

// mma.sync m16n8k16 fp16 -> fp32 accumulate
__device__ __forceinline__ void mma_fp16(float* c, const uint32_t* a, const uint32_t* b) {
    asm volatile(
        "mma.sync.aligned.m16n8k16.row.col.f32.f16.f16.f32 "
        "{%0,%1,%2,%3}, {%4,%5,%6,%7}, {%8,%9}, {%0,%1,%2,%3};"
        : "+f"(c[0]), "+f"(c[1]), "+f"(c[2]), "+f"(c[3])
        : "r"(a[0]), "r"(a[1]), "r"(a[2]), "r"(a[3]), "r"(b[0]), "r"(b[1]));
}

// Stage layout: BK=64 halves (128 B data/row), row stride 144 B (bank-free:
// 144/4 mod 32 = 4-bank shift per row -> 8 rows cover all 32 banks for LDSM).
// A rows 0..127 then B rows 0..127.
#define ROW_B 144
#define STAGE_BYTES (2 * 128 * ROW_B)        // 36864 B
#define NSTAGE 3
#define GEMM_SMEM (NSTAGE * STAGE_BYTES)     // 110592 B -> 2 CTA/SM (221 KB)

// ---------------------------------------------------------------------------
// Shared mainloop: 128x128 tile, BK=64, 3-stage cp.async, ldmatrix fragments.
// ---------------------------------------------------------------------------
__device__ __forceinline__ void gemm_mainloop(
    uint32_t sb,                             // smem byte address of stage 0
    const __half* __restrict__ Ablk, const __half* __restrict__ Bblk,
    int K, int tid, float acc[2][8][4])
{
    const int wid = tid >> 5, lane = tid & 31;
    const int wm = wid >> 1, wn = wid & 1;
    const int lm_r = lane & 15;              // row within 16-row block
    const int lm_k = (lane >> 4) * 16;       // +0 / +16 B (k-halves)

    auto load_stage = [&](int s, int kblk) {
        const __half* Asrc = Ablk + kblk * 64;
        const __half* Bsrc = Bblk + kblk * 64;
        uint32_t abase = sb + (uint32_t)s * STAGE_BYTES;
        uint32_t bbase = abase + 128 * ROW_B;
#pragma unroll
        for (int i = 0; i < 4; i++) {
            int idx = tid + i * 256;
            int row = idx >> 3, k16 = idx & 7;   // 8 x 16B chunks per 128B row
            CP_ASYNC16(abase + (uint32_t)(row * ROW_B + k16 * 16), Asrc + (size_t)row * K + k16 * 8);
            CP_ASYNC16(bbase + (uint32_t)(row * ROW_B + k16 * 16), Bsrc + (size_t)row * K + k16 * 8);
        }
        CP_COMMIT();
    };

#pragma unroll
    for (int mf = 0; mf < 2; mf++)
#pragma unroll
        for (int nf = 0; nf < 8; nf++)
#pragma unroll
            for (int j = 0; j < 4; j++) acc[mf][nf][j] = 0.f;

    const int nk = K >> 6;                   // K / 64 chunks
    load_stage(0, 0);
    if (nk > 1) load_stage(1, 1);

    for (int c = 0; c < nk; c++) {
        if (c + 1 < nk) CP_WAIT1(); else CP_WAIT0();
        __syncthreads();
        if (c + 2 < nk) load_stage((c + 2) % NSTAGE, c + 2);

        const uint32_t Ab = sb + (uint32_t)(c % NSTAGE) * STAGE_BYTES;
        const uint32_t Bb = Ab + 128 * ROW_B;

#pragma unroll
        for (int ks = 0; ks < 4; ks++) {     // four k16 steps per BK=64
            uint32_t a[2][4], b[8][2];
#pragma unroll
            for (int mf = 0; mf < 2; mf++) {
                uint32_t addr = Ab + (uint32_t)((wm * 32 + mf * 16 + lm_r) * ROW_B + ks * 32) + lm_k;
                LDSM_X4(a[mf][0], a[mf][1], a[mf][2], a[mf][3], addr);
            }
#pragma unroll
            for (int p = 0; p < 4; p++) {
                uint32_t addr = Bb + (uint32_t)((wn * 64 + p * 16 + lm_r) * ROW_B + ks * 32) + lm_k;
                LDSM_X4(b[2 * p][0], b[2 * p + 1][0], b[2 * p][1], b[2 * p + 1][1], addr);
            }
#pragma unroll
            for (int mf = 0; mf < 2; mf++)
#pragma unroll
                for (int nf = 0; nf < 8; nf++)
                    mma_fp16(acc[mf][nf], a[mf], b[nf]);
        }
    }
    __syncthreads();   // stages reused by caller epilogues
}

// ---------------------------------------------------------------------------
// Standard GEMM (dynamic smem, 2 CTA/SM): MODE 0 = fp32 out, MODE 1 = fp16 out
// ---------------------------------------------------------------------------
template <bool RELU, int MODE>
__global__ __launch_bounds__(256, 2) void gemm_std(
    const __half* __restrict__ A, const __half* __restrict__ Wt,
    const float* __restrict__ bias,
    float* __restrict__ Cf, __half* __restrict__ Ch,
    int M, int N, int K)
{
    extern __shared__ uint32_t dyn[];
    const uint32_t sb = smem_u32(dyn);
    const int tid = threadIdx.x;
    const int wid = tid >> 5, lane = tid & 31;
    const int g = lane >> 2, tg = lane & 3;
    const int wm = wid >> 1, wn = wid & 1;

    const size_t m0 = (size_t)blockIdx.y * 128;
    const size_t n0 = (size_t)blockIdx.x * 128;

    float acc[2][8][4];
    gemm_mainloop(sb, A + m0 * K, Wt + n0 * K, K, tid, acc);

#pragma unroll
    for (int mf = 0; mf < 2; mf++) {
        size_t row0 = m0 + wm * 32 + mf * 16 + g;
#pragma unroll
        for (int nf = 0; nf < 8; nf++) {
            int col = (int)n0 + wn * 64 + nf * 8 + tg * 2;
            float b0 = bias[col], b1 = bias[col + 1];
            float v0 = acc[mf][nf][0] + b0;
            float v1 = acc[mf][nf][1] + b1;
            float v2 = acc[mf][nf][2] + b0;
            float v3 = acc[mf][nf][3] + b1;
            if (RELU) { v0 = fmaxf(v0, 0.f); v1 = fmaxf(v1, 0.f); v2 = fmaxf(v2, 0.f); v3 = fmaxf(v3, 0.f); }
            if (MODE == 0) {
                *reinterpret_cast<float2*>(Cf + row0 * N + col)       = make_float2(v0, v1);
                *reinterpret_cast<float2*>(Cf + (row0 + 8) * N + col) = make_float2(v2, v3);
            } else {
                *reinterpret_cast<__half2*>(Ch + row0 * N + col)       = __floats2half2_rn(v0, v1);
                *reinterpret_cast<__half2*>(Ch + (row0 + 8) * N + col) = __floats2half2_rn(v2, v3);
            }
        }
    }
}

// ---------------------------------------------------------------------------
// kv GEMM with fused logits: grid (4, T/128), K = 256.
// n0 < 256: k-half -> dot fp32 accumulators against gathered q -> logit partials
// n0 >= 256: v-half -> fp16 store
// ---------------------------------------------------------------------------
#define QB_STRIDE 132                        // q tile [128][132] fp32 = 67584 B

__global__ __launch_bounds__(256, 2) void gemm_kv(
    const __half* __restrict__ A, const __half* __restrict__ Wt,
    const float* __restrict__ bias,
    __half* __restrict__ v_out, float* __restrict__ lpart,
    const float* __restrict__ q, const int* __restrict__ seg, int M)
{
    extern __shared__ uint32_t dyn[];
    __shared__ int   s_seg[128];
    __shared__ float s_logit[128];
    const uint32_t sb = smem_u32(dyn);

    const int tid = threadIdx.x;
    const int wid = tid >> 5, lane = tid & 31;
    const int g = lane >> 2, tg = lane & 3;
    const int wm = wid >> 1, wn = wid & 1;

    const size_t t0 = (size_t)blockIdx.y * 128;
    const int n0 = blockIdx.x * 128;
    const bool is_k = (n0 < 256);

    if (tid < 128) {
        if (is_k) s_seg[tid] = seg[t0 + tid];
        s_logit[tid] = 0.f;
    }

    float acc[2][8][4];
    gemm_mainloop(sb, A + t0 * H_DIM, Wt + (size_t)n0 * H_DIM, H_DIM, tid, acc);

    if (is_k) {
        // Gather q slice [128 rows][128 cols] into reused smem
        float* qb = (float*)dyn;
#pragma unroll
        for (int i = 0; i < 16; i++) {
            int idx = tid + i * 256;
            int row = idx >> 5, c16 = idx & 31;
            float4 v = *reinterpret_cast<const float4*>(
                q + (size_t)s_seg[row] * H_DIM + n0 + c16 * 4);
            *reinterpret_cast<float4*>(qb + row * QB_STRIDE + c16 * 4) = v;
        }
        __syncthreads();

#pragma unroll
        for (int mf = 0; mf < 2; mf++) {
            int rA = wm * 32 + mf * 16 + g;
            int rB = rA + 8;
            float pA = 0.f, pB = 0.f;
#pragma unroll
            for (int nf = 0; nf < 8; nf++) {
                int cq = wn * 64 + nf * 8 + tg * 2;
                int col = n0 + cq;
                float bb0 = __ldg(bias + col), bb1 = __ldg(bias + col + 1);
                float q0A = qb[rA * QB_STRIDE + cq], q1A = qb[rA * QB_STRIDE + cq + 1];
                float q0B = qb[rB * QB_STRIDE + cq], q1B = qb[rB * QB_STRIDE + cq + 1];
                pA = fmaf(acc[mf][nf][0] + bb0, q0A, pA);
                pA = fmaf(acc[mf][nf][1] + bb1, q1A, pA);
                pB = fmaf(acc[mf][nf][2] + bb0, q0B, pB);
                pB = fmaf(acc[mf][nf][3] + bb1, q1B, pB);
            }
            pA += __shfl_xor_sync(0xffffffffu, pA, 1);
            pA += __shfl_xor_sync(0xffffffffu, pA, 2);
            pB += __shfl_xor_sync(0xffffffffu, pB, 1);
            pB += __shfl_xor_sync(0xffffffffu, pB, 2);
            if (tg == 0) {
                atomicAdd(s_logit + rA, pA);
                atomicAdd(s_logit + rB, pB);
            }
        }
        __syncthreads();
        if (tid < 128)
            lpart[(size_t)blockIdx.x * M + t0 + tid] = s_logit[tid] * 0.0625f;
    } else {
#pragma unroll
        for (int mf = 0; mf < 2; mf++) {
            size_t r0 = t0 + wm * 32 + mf * 16 + g;
#pragma unroll
            for (int nf = 0; nf < 8; nf++) {
                int col = n0 + wn * 64 + nf * 8 + tg * 2;
                float bb0 = __ldg(bias + col), bb1 = __ldg(bias + col + 1);
                int vc = col - 256;
                *reinterpret_cast<__half2*>(v_out + r0 * H_DIM + vc) =
                    __floats2half2_rn(acc[mf][nf][0] + bb0, acc[mf][nf][1] + bb1);
                *reinterpret_cast<__half2*>(v_out + (r0 + 8) * H_DIM + vc) =
                    __floats2half2_rn(acc[mf][nf][2] + bb0, acc[mf][nf][3] + bb1);
            }
        }
    }
}

// ---------------------------------------------------------------------------
// One merged prep kernel: obj cvt | ctx cvt | 4 weight transposes | segstart
// (branch by blockIdx range; small parts run concurrently with the big cvt)
// ---------------------------------------------------------------------------
#define OBJ_BLK   (T_MAX * F_DIM / 4 / 256)            // 32768
#define CTX_BLK   (B_MAX * C_DIM / 4 / 256)            // 512
#define W1_BLK    (F_DIM * H_DIM / 256)                // 128
#define W2_BLK    (H_DIM * H_DIM / 256)                // 256
#define W3_BLK    (H_DIM * KV_DIM / 256)               // 512
#define WQ_BLK    (C_DIM * H_DIM / 256)                // 512
#define SEG_BLK   (T_MAX / 256)                        // 1024
#define PREP_BLOCKS (OBJ_BLK + CTX_BLK + W1_BLK + W2_BLK + W3_BLK + WQ_BLK + SEG_BLK)

__device__ __forceinline__ void cvt_range(const float* in, __half* out, int i) {
    float4 v = reinterpret_cast<const float4*>(in)[i];
    reinterpret_cast<__half2*>(out)[i * 2]     = __floats2half2_rn(v.x, v.y);
    reinterpret_cast<__half2*>(out)[i * 2 + 1] = __floats2half2_rn(v.z, v.w);
}
__device__ __forceinline__ void tr_range(const float* W, __half* Wt, int K, int N, int i) {
    int k = i / N, n = i - k * N;
    Wt[(size_t)n * K + k] = __float2half_rn(W[i]);
}

__global__ void prep_all(
    const float* __restrict__ objects, const float* __restrict__ context,
    const float* __restrict__ W1, const float* __restrict__ W2,
    const float* __restrict__ W3, const float* __restrict__ Wq,
    const int* __restrict__ seg, int T, int B)
{
    int b = blockIdx.x;
    int t = threadIdx.x;
    if (b < OBJ_BLK) { cvt_range(objects, g_objh, b * 256 + t); return; }
    b -= OBJ_BLK;
    if (b < CTX_BLK) { cvt_range(context, g_ctxh, b * 256 + t); return; }
    b -= CTX_BLK;
    if (b < W1_BLK) { tr_range(W1, g_Wt1, F_DIM, H_DIM, b * 256 + t); return; }
    b -= W1_BLK;
    if (b < W2_BLK) { tr_range(W2, g_Wt2, H_DIM, H_DIM, b * 256 + t); return; }
    b -= W2_BLK;
    if (b < W3_BLK) { tr_range(W3, g_Wt3, H_DIM, KV_DIM, b * 256 + t); return; }
    b -= W3_BLK;
    if (b < WQ_BLK) { tr_range(Wq, g_Wtq, C_DIM, H_DIM, b * 256 + t); return; }
    b -= WQ_BLK;
    {   // segstart
        int i = b * 256 + t;
        if (i == 0) { g_segstart[seg[0]] = 0; g_segstart[B] = T; }
        if (i > 0 && i < T) {
            int s = seg[i];
            if (s != seg[i - 1]) g_segstart[s] = i;
        }
    }
}

// ---------------------------------------------------------------------------
// Per-segment softmax + weighted value sum. One 256-thread block per segment.
// ---------------------------------------------------------------------------
__global__ __launch_bounds__(256) void segreduce_kernel(
    const float* __restrict__ lp0, const float* __restrict__ lp1,
    float* __restrict__ emb, float* __restrict__ wout)
{
    const int s = blockIdx.x;
    const int s0 = g_segstart[s];
    const int s1 = g_segstart[s + 1];
    const int tid = threadIdx.x;

    __shared__ float red[8];
    __shared__ float bcast;

    float m = -INFINITY;
    for (int t = s0 + tid; t < s1; t += 256) m = fmaxf(m, lp0[t] + lp1[t]);
#pragma unroll
    for (int o = 16; o; o >>= 1) m = fmaxf(m, __shfl_xor_sync(0xffffffffu, m, o));
    if ((tid & 31) == 0) red[tid >> 5] = m;
    __syncthreads();
    if (tid == 0) {
        float mm = red[0];
#pragma unroll
        for (int i = 1; i < 8; i++) mm = fmaxf(mm, red[i]);
        bcast = mm;
    }
    __syncthreads();
    m = bcast;
    __syncthreads();

    float z = 0.f;
    for (int t = s0 + tid; t < s1; t += 256) z += __expf(lp0[t] + lp1[t] - m);
#pragma unroll
    for (int o = 16; o; o >>= 1) z += __shfl_xor_sync(0xffffffffu, z, o);
    if ((tid & 31) == 0) red[tid >> 5] = z;
    __syncthreads();
    if (tid == 0) {
        float zz = 0.f;
#pragma unroll
        for (int i = 0; i < 8; i++) zz += red[i];
        bcast = zz;
    }
    __syncthreads();
    const float inv = 1.f / bcast;
    __syncthreads();

    for (int t = s0 + tid; t < s1; t += 256) wout[t] = __expf(lp0[t] + lp1[t] - m) * inv;
    __syncthreads();

    float acc = 0.f;
    for (int t = s0; t < s1; t++) {
        float w = wout[t];
        acc = fmaf(w, __half2float(g_vh[(size_t)t * H_DIM + tid]), acc);
    }
    emb[(size_t)s * H_DIM + tid] = acc;
}

// ---------------------------------------------------------------------------
// Launch
// ---------------------------------------------------------------------------
extern "C" void kernel_launch(void* const* d_in, const int* in_sizes, int n_in,
                              void* d_out, int out_size)
{
    const float* objects = (const float*)d_in[0];
    const float* context = (const float*)d_in[1];
    const int*   seg     = (const int*)  d_in[2];
    const float* W1 = (const float*)d_in[3];
    const float* b1 = (const float*)d_in[4];
    const float* W2 = (const float*)d_in[5];
    const float* b2 = (const float*)d_in[6];
    const float* W3 = (const float*)d_in[7];
    const float* b3 = (const float*)d_in[8];
    const float* Wq = (const float*)d_in[9];
    const float* bq = (const float*)d_in[10];

    const int T = in_sizes[2];                 // 262144
    const int B = in_sizes[1] / C_DIM;         // 4096

    float* out = (float*)d_out;
    float* emb_out = out;
    float* w_out   = out + (size_t)B * H_DIM;

    __half *p_objh, *p_ctxh, *p_h1, *p_h2, *p_vh, *p_w1, *p_w2, *p_w3, *p_wq;
    float *p_q, *p_lp;
    cudaGetSymbolAddress((void**)&p_objh, g_objh);
    cudaGetSymbolAddress((void**)&p_ctxh, g_ctxh);
    cudaGetSymbolAddress((void**)&p_h1, g_h1);
    cudaGetSymbolAddress((void**)&p_h2, g_h2);
    cudaGetSymbolAddress((void**)&p_vh, g_vh);
    cudaGetSymbolAddress((void**)&p_q,  g_q);
    cudaGetSymbolAddress((void**)&p_lp, g_lp);
    cudaGetSymbolAddress((void**)&p_w1, g_Wt1);
    cudaGetSymbolAddress((void**)&p_w2, g_Wt2);
    cudaGetSymbolAddress((void**)&p_w3, g_Wt3);
    cudaGetSymbolAddress((void**)&p_wq, g_Wtq);

    cudaFuncSetAttribute(gemm_std<false, 0>, cudaFuncAttributeMaxDynamicSharedMemorySize, GEMM_SMEM);
    cudaFuncSetAttribute(gemm_std<true, 1>,  cudaFuncAttributeMaxDynamicSharedMemorySize, GEMM_SMEM);
    cudaFuncSetAttribute(gemm_kv, cudaFuncAttributeMaxDynamicSharedMemorySize, GEMM_SMEM);

    // All prep in one launch
    prep_all<<<PREP_BLOCKS, 256>>>(objects, context, W1, W2, W3, Wq, seg, T, B);

    // q = context @ Wq + bq  [4096,512]->[4096,256] fp32 out
    gemm_std<false, 0><<<dim3(H_DIM / 128, B / 128), 256, GEMM_SMEM>>>(
        p_ctxh, p_wq, bq, p_q, nullptr, B, H_DIM, C_DIM);
    // h1 = relu(objects @ W1 + b1)  fp16 out
    gemm_std<true, 1><<<dim3(H_DIM / 128, T / 128), 256, GEMM_SMEM>>>(
        p_objh, p_w1, b1, nullptr, p_h1, T, H_DIM, F_DIM);
    // h2 = relu(h1 @ W2 + b2)  fp16 out
    gemm_std<true, 1><<<dim3(H_DIM / 128, T / 128), 256, GEMM_SMEM>>>(
        p_h1, p_w2, b2, nullptr, p_h2, T, H_DIM, H_DIM);
    // kv: k-halves -> fused logit partials, v-halves -> g_vh (fp16)
    gemm_kv<<<dim3(KV_DIM / 128, T / 128), 256, GEMM_SMEM>>>(
        p_h2, p_w3, b3, p_vh, p_lp, p_q, seg, T);

    segreduce_kernel<<<B, 256>>>(p_lp, p_lp + T, emb_out, w_out);
}